// round 5
// baseline (speedup 1.0000x reference)
#include <cuda_runtime.h>
#include <cuda_fp16.h>
#include <cstdint>

// Problem constants: B=4, H=64, W=2650, C=64, N=680000
#define PB 4
#define PH 64
#define PW 2650
#define PC 64
#define PHW (PH * PW)          // 169600
#define THR 0.5f

// Scratch for BCHW -> BHWC transposed features, fp16 (~87 MB).
__device__ __half g_featsT[(size_t)PB * PHW * PC];

// ---------------------------------------------------------------------------
// Kernel 1: mask-aware transpose [B, C, HW] f32 -> [B, HW, C] f16
// (unchanged from R4 — known good, ~80% of practical DRAM ceiling)
// ---------------------------------------------------------------------------
__global__ __launch_bounds__(256) void transpose_bchw_bhwc(
    const float* __restrict__ rf,
    const float* __restrict__ seg)
{
    __shared__ float s[32 * 65];

    const int b      = blockIdx.y;
    const int hwBase = blockIdx.x * 32;

    const int t  = threadIdx.x;
    const int cR = t >> 3;                // 0..31
    const int f4 = t & 7;                 // 0..7

    const float* src = rf + (size_t)b * PC * PHW + hwBase;

#pragma unroll
    for (int half_ = 0; half_ < 2; half_++) {
        const int c = cR + half_ * 32;
        const float4 v = __ldg((const float4*)(src + (size_t)c * PHW) + f4);
        s[(f4 * 4 + 0) * 65 + c] = v.x;
        s[(f4 * 4 + 1) * 65 + c] = v.y;
        s[(f4 * 4 + 2) * 65 + c] = v.z;
        s[(f4 * 4 + 3) * 65 + c] = v.w;
    }
    __syncthreads();

    const int row = t >> 3;               // 0..31
    const int q   = t & 7;                // 0..7
    const bool fg = __ldg(&seg[(size_t)b * PHW + hwBase + row]) >= THR;
    if (fg) {
        const float* sr = s + row * 65 + q * 8;
        half2 h0 = __floats2half2_rn(sr[0], sr[1]);
        half2 h1 = __floats2half2_rn(sr[2], sr[3]);
        half2 h2 = __floats2half2_rn(sr[4], sr[5]);
        half2 h3 = __floats2half2_rn(sr[6], sr[7]);
        uint4 pack;
        pack.x = *(const unsigned*)&h0;
        pack.y = *(const unsigned*)&h1;
        pack.z = *(const unsigned*)&h2;
        pack.w = *(const unsigned*)&h3;
        uint4* dst = (uint4*)(g_featsT + ((size_t)b * PHW + hwBase + row) * PC);
        dst[q] = pack;
    }
}

// ---------------------------------------------------------------------------
// Kernel 2: 16 points per warp (MLP=16), fp16 reads, direct writes.
//  - lanes 0..15 run the index chain for 16 points in parallel
//  - 16 independent 128B half2 gathers per warp, bg points skipped (zeros)
//  - register-lean: only v[16] kept live; mask re-shuffled on demand
// ---------------------------------------------------------------------------
__global__ __launch_bounds__(256) void point_gather(
    const float* __restrict__ points,
    const int*   __restrict__ ri,
    const float* __restrict__ seg,
    float*       __restrict__ out,
    float*       __restrict__ mask_out,
    int n)
{
    const int tid   = threadIdx.x;
    const int warp  = tid >> 5;
    const int lane  = tid & 31;
    const int pBase = blockIdx.x * 128 + warp * 16;

    // --- index chain for 16 points on lanes 0..15 ---
    int   flat_i = 0;
    float m16    = 0.f;
    if (lane < 16) {
        const int p = pBase + lane;
        if (p < n) {
            const int b = (int)__ldg(&points[(size_t)p * 5]);
            const int r = __ldg(&ri[p * 2 + 0]);
            const int c = __ldg(&ri[p * 2 + 1]);
            flat_i = b * PHW + r * PW + c;
            m16 = (__ldg(&seg[flat_i]) >= THR) ? 1.0f : 0.0f;
        }
    }

    // --- 16 independent half2 feature gathers (MLP=16 per lane) ---
    half2 v[16];
#pragma unroll
    for (int k = 0; k < 16; k++) {
        const int   fl = __shfl_sync(0xffffffffu, flat_i, k);
        const float m  = __shfl_sync(0xffffffffu, m16,    k);
        v[k] = __floats2half2_rn(0.f, 0.f);
        if (m != 0.f)
            v[k] = __ldg((const half2*)(g_featsT + (size_t)fl * PC) + lane);
    }

    // --- feature writeback: per-point contiguous ~256B warp stores ---
#pragma unroll
    for (int k = 0; k < 16; k++) {
        const int p = pBase + k;
        if (p < n) {
            const float2 f = __half22float2(v[k]);
            float* row = out + (size_t)p * 69 + 5;
            row[2 * lane + 0] = f.x;
            row[2 * lane + 1] = f.y;
        }
    }

    // --- point columns 0..4 (masked): 16 points x 5 cols = 80 values ---
#pragma unroll
    for (int half_ = 0; half_ < 3; half_++) {
        const int idx = half_ * 32 + lane;       // 0..95, use 0..79
        if (idx < 80) {
            const int k = idx / 5;
            const int j = idx - k * 5;
            const float m = __shfl_sync(0xffffffffu, m16, k);
            const int p = pBase + k;
            if (p < n)
                out[(size_t)p * 69 + j] = __ldg(&points[(size_t)p * 5 + j]) * m;
        }
    }

    // --- mask output: lanes 0..15 ---
    if (lane < 16 && mask_out != nullptr && (pBase + lane) < n)
        mask_out[pBase + lane] = m16;
}

// ---------------------------------------------------------------------------
// Launch
// ---------------------------------------------------------------------------
extern "C" void kernel_launch(void* const* d_in, const int* in_sizes, int n_in,
                              void* d_out, int out_size)
{
    const float* points = (const float*)d_in[0];
    const int*   ri     = (const int*)  d_in[1];
    const float* seg    = (const float*)d_in[2];
    const float* rf     = (const float*)d_in[3];

    float* out = (float*)d_out;
    const int n = in_sizes[0] / 5;   // N = 680000

    float* mask_out = nullptr;
    if ((long long)out_size >= (long long)n * 70)
        mask_out = out + (size_t)n * 69;

    // Kernel 1: mask-aware transpose (f32 -> f16 scratch)
    {
        dim3 grid(PHW / 32, PB, 1);   // (5300, 4)
        transpose_bchw_bhwc<<<grid, 256>>>(rf, seg);
    }

    // Kernel 2: gather (16 points per warp, half2 reads, direct writes)
    {
        const int blocks = (n + 127) / 128;   // 5313
        point_gather<<<blocks, 256>>>(points, ri, seg, out, mask_out, n);
    }
}

// round 6
// speedup vs baseline: 1.1859x; 1.1859x over previous
#include <cuda_runtime.h>
#include <cuda_fp16.h>
#include <cstdint>

// Problem constants: B=4, H=64, W=2650, C=64, N=680000
#define PB 4
#define PH 64
#define PW 2650
#define PC 64
#define PHW (PH * PW)          // 169600
#define THR 0.5f

// Scratch for BCHW -> BHWC transposed features, fp16 (~87 MB; fg rows ~44 MB).
__device__ __half g_featsT[(size_t)PB * PHW * PC];

// ---------------------------------------------------------------------------
// Kernel 1: mask-aware transpose [B, C, HW] f32 -> [B, HW, C] f16
// 64 hw x 64 C tile, 256 threads. __ldcs streaming loads (don't pollute L2),
// normal stores (allocate scratch in L2 for the gather to hit).
// ---------------------------------------------------------------------------
__global__ __launch_bounds__(256) void transpose_bchw_bhwc(
    const float* __restrict__ rf,
    const float* __restrict__ seg)
{
    __shared__ float s[64 * 65];          // [hw][c] padded
    __shared__ float sseg[64];

    const int b      = blockIdx.y;
    const int hwBase = blockIdx.x * 64;
    const int t      = threadIdx.x;

    if (t < 64)
        sseg[t] = __ldg(&seg[(size_t)b * PHW + hwBase + t]);

    const float* src = rf + (size_t)b * PC * PHW + hwBase;

    // --- load: 64 c-rows x 64 hw floats, float4 streaming, coalesced ---
    const int cRow = t >> 4;              // 0..15
    const int f4   = t & 15;              // 0..15
#pragma unroll
    for (int pass = 0; pass < 4; pass++) {
        const int c = cRow + pass * 16;
        const float4 v = __ldcs((const float4*)(src + (size_t)c * PHW) + f4);
        s[(f4 * 4 + 0) * 65 + c] = v.x;
        s[(f4 * 4 + 1) * 65 + c] = v.y;
        s[(f4 * 4 + 2) * 65 + c] = v.z;
        s[(f4 * 4 + 3) * 65 + c] = v.w;
    }
    __syncthreads();

    // --- write: 64 hw-rows x 64 halves (128B/row), fg-gated ---
    const int q = t & 7;                  // 0..7 : uint4 within row
#pragma unroll
    for (int pass = 0; pass < 2; pass++) {
        const int row = (t >> 3) + pass * 32;   // 0..63
        if (sseg[row] >= THR) {
            const float* sr = s + row * 65 + q * 8;
            half2 h0 = __floats2half2_rn(sr[0], sr[1]);
            half2 h1 = __floats2half2_rn(sr[2], sr[3]);
            half2 h2 = __floats2half2_rn(sr[4], sr[5]);
            half2 h3 = __floats2half2_rn(sr[6], sr[7]);
            uint4 pack;
            pack.x = *(const unsigned*)&h0;
            pack.y = *(const unsigned*)&h1;
            pack.z = *(const unsigned*)&h2;
            pack.w = *(const unsigned*)&h3;
            uint4* dst = (uint4*)(g_featsT + ((size_t)b * PHW + hwBase + row) * PC);
            dst[q] = pack;
        }
    }
}

// ---------------------------------------------------------------------------
// Kernel 2: 8 points per warp (R4 config), fp16 feature reads (L2 hits),
// __stcs evict-first output stores so the stream doesn't evict the scratch.
// ---------------------------------------------------------------------------
__global__ __launch_bounds__(256) void point_gather(
    const float* __restrict__ points,
    const int*   __restrict__ ri,
    const float* __restrict__ seg,
    float*       __restrict__ out,
    float*       __restrict__ mask_out,
    int n)
{
    const int tid   = threadIdx.x;
    const int warp  = tid >> 5;
    const int lane  = tid & 31;
    const int pBase = blockIdx.x * 64 + warp * 8;

    // --- index chain for 8 points on lanes 0..7 ---
    int   flat_i = 0;
    float m8     = 0.f;
    if (lane < 8) {
        const int p = pBase + lane;
        if (p < n) {
            const int b = (int)__ldg(&points[(size_t)p * 5]);
            const int r = __ldg(&ri[p * 2 + 0]);
            const int c = __ldg(&ri[p * 2 + 1]);
            flat_i = b * PHW + r * PW + c;
            m8 = (__ldg(&seg[flat_i]) >= THR) ? 1.0f : 0.0f;
        }
    }

    // --- 8 independent half2 feature gathers (MLP=8 per lane) ---
    half2 v[8];
    float ms[8];
#pragma unroll
    for (int k = 0; k < 8; k++) {
        const int fl = __shfl_sync(0xffffffffu, flat_i, k);
        ms[k]        = __shfl_sync(0xffffffffu, m8,     k);
        v[k] = __floats2half2_rn(0.f, 0.f);
        if (ms[k] != 0.f)
            v[k] = __ldg((const half2*)(g_featsT + (size_t)fl * PC) + lane);
    }

    // --- feature writeback: per-point contiguous warp stores, evict-first ---
#pragma unroll
    for (int k = 0; k < 8; k++) {
        const int p = pBase + k;
        if (p < n) {
            const float2 f = __half22float2(v[k]);
            float* row = out + (size_t)p * 69 + 5;
            __stcs(&row[2 * lane + 0], f.x);
            __stcs(&row[2 * lane + 1], f.y);
        }
    }

    // --- point columns 0..4 (masked): 8 points x 5 cols = 40 values ---
#pragma unroll
    for (int half_ = 0; half_ < 2; half_++) {
        const int idx = half_ * 32 + lane;
        if (idx < 40) {
            const int k = idx / 5;
            const int j = idx - k * 5;
            const int p = pBase + k;
            if (p < n)
                __stcs(&out[(size_t)p * 69 + j],
                       __ldg(&points[(size_t)p * 5 + j]) * ms[k]);
        }
    }

    // --- mask output ---
    if (lane < 8 && mask_out != nullptr && (pBase + lane) < n)
        __stcs(&mask_out[pBase + lane], m8);
}

// ---------------------------------------------------------------------------
// Launch
// ---------------------------------------------------------------------------
extern "C" void kernel_launch(void* const* d_in, const int* in_sizes, int n_in,
                              void* d_out, int out_size)
{
    const float* points = (const float*)d_in[0];
    const int*   ri     = (const int*)  d_in[1];
    const float* seg    = (const float*)d_in[2];
    const float* rf     = (const float*)d_in[3];

    float* out = (float*)d_out;
    const int n = in_sizes[0] / 5;   // N = 680000

    float* mask_out = nullptr;
    if ((long long)out_size >= (long long)n * 70)
        mask_out = out + (size_t)n * 69;

    // Kernel 1: mask-aware transpose (f32 -> f16 scratch, L2-resident)
    {
        dim3 grid(PHW / 64, PB, 1);   // (2650, 4)
        transpose_bchw_bhwc<<<grid, 256>>>(rf, seg);
    }

    // Kernel 2: gather (8 points per warp, L2-hit feature reads)
    {
        const int blocks = (n + 63) / 64;   // 10625
        point_gather<<<blocks, 256>>>(points, ri, seg, out, mask_out, n);
    }
}